// round 1
// baseline (speedup 1.0000x reference)
#include <cuda_runtime.h>
#include <cuda_bf16.h>
#include <cstdint>

#define NN 6144
#define IN_DIM 512
#define CHANNELS 4
#define C_DIM 64
#define FDIM 256          // CHANNELS * C_DIM
#define CAP 128           // max neighbors per row (mean ~31, sigma ~5.5 -> safe)

// -------- scratch (device globals; no allocation allowed) --------
__device__ float g_featsA[(size_t)NN * FDIM];
__device__ float g_featsB[(size_t)NN * FDIM];
__device__ int   g_ell[(size_t)NN * CAP];
__device__ int   g_deg[NN];

// ============================================================
// Kernel 1: dense adj -> ELL (order-preserving, deterministic)
// one warp per row, ballot+popc compaction
// ============================================================
__global__ __launch_bounds__(256) void build_ell_kernel(const int* __restrict__ adj) {
    int row = blockIdx.x * 8 + (threadIdx.x >> 5);
    if (row >= NN) return;
    int lane = threadIdx.x & 31;
    const int* arow = adj + (size_t)row * NN;
    int total = 0;
    unsigned lt_mask = (1u << lane) - 1u;
    for (int base = 0; base < NN; base += 32) {
        int v = arow[base + lane];
        unsigned bal = __ballot_sync(0xffffffffu, v > 0);
        if (v > 0) {
            int pos = total + __popc(bal & lt_mask);
            if (pos < CAP) g_ell[(size_t)row * CAP + pos] = base + lane;
        }
        total += __popc(bal);
    }
    if (lane == 0) g_deg[row] = total < CAP ? total : CAP;
}

// ============================================================
// Kernel 2: feats0 = l2norm(features @ W + b), layout [n][c*64+k]
// Block tile: 64 rows x 64 cols (= exactly one channel), 256 threads,
// 4x4 microtile per thread, BK=16.
// ============================================================
__global__ __launch_bounds__(256) void project_kernel(const float* __restrict__ feat,
                                                      const float* __restrict__ W,
                                                      const float* __restrict__ bias) {
    __shared__ float sA[16][64];   // [d][row]
    __shared__ float sB[16][64];   // [d][k]
    __shared__ float s_scale[64];

    const int c  = blockIdx.y;
    const int n0 = blockIdx.x * 64;
    const int t  = threadIdx.x;
    const int tx = t & 15, ty = t >> 4;

    float acc[4][4];
#pragma unroll
    for (int i = 0; i < 4; i++)
#pragma unroll
        for (int j = 0; j < 4; j++) acc[i][j] = 0.f;

    const float* Wc = W + (size_t)c * IN_DIM * C_DIM;

    const int lrow = t >> 2, lseg = t & 3;   // A-tile loader mapping
    const int ld   = t >> 4, lks  = t & 15;  // B-tile loader mapping

    for (int d0 = 0; d0 < IN_DIM; d0 += 16) {
        float4 a = *(const float4*)(feat + (size_t)(n0 + lrow) * IN_DIM + d0 + lseg * 4);
        sA[lseg * 4 + 0][lrow] = a.x;
        sA[lseg * 4 + 1][lrow] = a.y;
        sA[lseg * 4 + 2][lrow] = a.z;
        sA[lseg * 4 + 3][lrow] = a.w;
        float4 bv = *(const float4*)(Wc + (size_t)(d0 + ld) * C_DIM + lks * 4);
        *(float4*)&sB[ld][lks * 4] = bv;
        __syncthreads();
#pragma unroll
        for (int d = 0; d < 16; d++) {
            float4 av = *(float4*)&sA[d][ty * 4];
            float4 bv2 = *(float4*)&sB[d][tx * 4];
            float ar[4] = {av.x, av.y, av.z, av.w};
            float br[4] = {bv2.x, bv2.y, bv2.z, bv2.w};
#pragma unroll
            for (int i = 0; i < 4; i++)
#pragma unroll
                for (int j = 0; j < 4; j++) acc[i][j] += ar[i] * br[j];
        }
        __syncthreads();
    }

    // bias + per-row sum of squares
    float4 bb4 = *(const float4*)(bias + c * C_DIM + tx * 4);
    float bb[4] = {bb4.x, bb4.y, bb4.z, bb4.w};
    float ss[4];
#pragma unroll
    for (int i = 0; i < 4; i++) {
        float s = 0.f;
#pragma unroll
        for (int j = 0; j < 4; j++) {
            acc[i][j] += bb[j];
            s += acc[i][j] * acc[i][j];
        }
        ss[i] = s;
    }
    // reduce across tx (16 lanes within half-warp; xor 1,2,4,8 stays in-half)
#pragma unroll
    for (int off = 1; off < 16; off <<= 1)
#pragma unroll
        for (int i = 0; i < 4; i++) ss[i] += __shfl_xor_sync(0xffffffffu, ss[i], off);
    if (tx == 0) {
#pragma unroll
        for (int i = 0; i < 4; i++) s_scale[ty * 4 + i] = rsqrtf(fmaxf(ss[i], 1e-24f));
    }
    __syncthreads();
#pragma unroll
    for (int i = 0; i < 4; i++) {
        float s = s_scale[ty * 4 + i];
        float4 o = make_float4(acc[i][0] * s, acc[i][1] * s, acc[i][2] * s, acc[i][3] * s);
        *(float4*)(g_featsA + (size_t)(n0 + ty * 4 + i) * FDIM + c * C_DIM + tx * 4) = o;
    }
}

// ============================================================
// Kernel 3: one attention+aggregate+renorm iteration.
// Block = 1 node, 256 threads = 8 warps; each warp handles every
// 8th neighbor independently. Lane l owns features [8l, 8l+8)
// (channel = l>>3), so neighbor rows load as 2 coalesced LDG.128.
// ============================================================
__global__ __launch_bounds__(256) void iterate_kernel(int pass, float* __restrict__ d_final) {
    const float* src = (pass == 1) ? g_featsB : g_featsA;
    float* dst = (pass == 0) ? g_featsB : (pass == 1) ? g_featsA : d_final;

    const int n = blockIdx.x;
    const int t = threadIdx.x;
    const int w = t >> 5, lane = t & 31;

    __shared__ float wacc[8][FDIM];
    __shared__ int   s_cols[CAP];
    __shared__ float wsum[8];

    const int d = g_deg[n];
    if (t < d) s_cols[t] = g_ell[(size_t)n * CAP + t];
    __syncthreads();

    const float* xrow = src + (size_t)n * FDIM;
    float4 x0 = *(const float4*)(xrow + lane * 8);
    float4 x1 = *(const float4*)(xrow + lane * 8 + 4);
    float4 a0 = make_float4(0.f, 0.f, 0.f, 0.f);
    float4 a1 = make_float4(0.f, 0.f, 0.f, 0.f);

    for (int i = w; i < d; i += 8) {
        int m = s_cols[i];
        const float* yrow = src + (size_t)m * FDIM;
        float4 y0 = *(const float4*)(yrow + lane * 8);
        float4 y1 = *(const float4*)(yrow + lane * 8 + 4);
        float p = x0.x * y0.x + x0.y * y0.y + x0.z * y0.z + x0.w * y0.w +
                  x1.x * y1.x + x1.y * y1.y + x1.z * y1.z + x1.w * y1.w;
        // reduce within 8-lane channel group
        p += __shfl_xor_sync(0xffffffffu, p, 1);
        p += __shfl_xor_sync(0xffffffffu, p, 2);
        p += __shfl_xor_sync(0xffffffffu, p, 4);
        float s0 = p;                                    // my channel's dot
        float s1 = __shfl_xor_sync(0xffffffffu, s0, 8);  // channel c^1
        float s2 = __shfl_xor_sync(0xffffffffu, s0, 16); // channel c^2
        float s3 = __shfl_xor_sync(0xffffffffu, s1, 16); // channel c^3
        float mx = fmaxf(fmaxf(s0, s1), fmaxf(s2, s3));
        float e0 = __expf(s0 - mx);
        float e1 = __expf(s1 - mx);
        float e2 = __expf(s2 - mx);
        float e3 = __expf(s3 - mx);
        float wgt = e0 / (e0 + e1 + e2 + e3);            // softmax across channels
        a0.x += wgt * y0.x; a0.y += wgt * y0.y; a0.z += wgt * y0.z; a0.w += wgt * y0.w;
        a1.x += wgt * y1.x; a1.y += wgt * y1.y; a1.z += wgt * y1.z; a1.w += wgt * y1.w;
    }

    *(float4*)&wacc[w][lane * 8]     = a0;
    *(float4*)&wacc[w][lane * 8 + 4] = a1;
    __syncthreads();

    // combine 8 warps' partials (fixed order -> deterministic), + self
    float val = xrow[t];
#pragma unroll
    for (int ww = 0; ww < 8; ww++) val += wacc[ww][t];

    // per-channel L2 norm: channel = t>>6 spans 2 warps
    float sq = val * val;
#pragma unroll
    for (int off = 16; off; off >>= 1) sq += __shfl_xor_sync(0xffffffffu, sq, off);
    if (lane == 0) wsum[w] = sq;
    __syncthreads();
    int c = t >> 6;
    float ssum = wsum[2 * c] + wsum[2 * c + 1];
    float scale = rsqrtf(fmaxf(ssum, 1e-24f));
    dst[(size_t)n * FDIM + t] = val * scale;
}

// ============================================================
extern "C" void kernel_launch(void* const* d_in, const int* in_sizes, int n_in,
                              void* d_out, int out_size) {
    const float* features = (const float*)d_in[0];   // [6144, 512]
    const int*   adj      = (const int*)d_in[1];     // [6144, 6144]
    const float* W        = (const float*)d_in[2];   // [4, 512, 64]
    const float* b        = (const float*)d_in[3];   // [4, 1, 64]
    float* out = (float*)d_out;                      // [6144, 256]

    build_ell_kernel<<<NN / 8, 256>>>(adj);
    project_kernel<<<dim3(NN / 64, CHANNELS), 256>>>(features, W, b);
    iterate_kernel<<<NN, 256>>>(0, out);
    iterate_kernel<<<NN, 256>>>(1, out);
    iterate_kernel<<<NN, 256>>>(2, out);
}